// round 3
// baseline (speedup 1.0000x reference)
#include <cuda_runtime.h>
#include <cstdint>

typedef unsigned long long ull;

#define B_TOT 1024
#define T_LEN 512
#define NU    64
#define NB    8
#define NCTA  128
#define THR   512
#define APITCH 20   // floats per A row (16 used + 4 pad); 80B keeps 16B alignment

// Layer activation ping-pong buffer: h[b][t][u], 128 MiB.
__device__ float g_h[(size_t)B_TOT * T_LEN * NU];

__device__ __forceinline__ ull ffma2(ull a, ull b, ull c) {
    ull d;
    asm("fma.rn.f32x2 %0, %1, %2, %3;" : "=l"(d) : "l"(a), "l"(b), "l"(c));
    return d;
}
// sigmoid(x) = 0.5*tanh(0.5x) + 0.5 : one MUFU + FMA
__device__ __forceinline__ float sigf(float x) {
    float t;
    asm("tanh.approx.f32 %0, %1;" : "=f"(t) : "f"(0.5f * x));
    return fmaf(0.5f, t, 0.5f);
}

// KX = input feature rows (1 for layer0, 64 otherwise). KTOT = KX + 64.
// LAST: only write g_h at t == T_LEN-1.
template <int KX, bool LAST>
__global__ void __launch_bounds__(THR, 1)
lstm_layer(const float* __restrict__ xin, const float* __restrict__ Wx,
           const float* __restrict__ U,   const float* __restrict__ bias)
{
    constexpr int KTOT = KX + NU;
    extern __shared__ float sm[];
    float* Wsh = sm;                      // [KTOT][256]
    float* Ash = Wsh + KTOT * 256;        // [KTOT][APITCH]: 8 duplicated (a,a) pairs
    float* Zsh = Ash + KTOT * APITCH;     // [8][256]

    const int tid = threadIdx.x;
    const int j2  = tid & 127;            // column pair: cols 2*j2, 2*j2+1
    const int rq  = tid >> 7;             // row quad 0..3 -> batch rows 2rq, 2rq+1
    const int bg0 = blockIdx.x * NB;

    // ---- stage weights: rows 0..KX-1 = Wx, rows KX..KTOT-1 = U ----
    for (int i = tid; i < KTOT * 256; i += THR) {
        int r = i >> 8, c = i & 255;
        Wsh[i] = (r < KX) ? Wx[i] : U[(r - KX) * 256 + c];
    }
    // zero h rows of A (h0 = 0)
    for (int i = tid; i < NU * APITCH; i += THR) Ash[KX * APITCH + i] = 0.0f;

    const ull bpair = *(const ull*)(bias + 2 * j2);

    // epilogue: one cell per thread: (batch eb, unit eu)
    const int eb = tid >> 6;              // 0..7
    const int eu = tid & 63;
    float cs = 0.0f;

    // ---- initial prefetch (t = 0) ----
    float xv = 0.0f, v = 0.0f;
    if (KX == 1) {
        if (tid < NB) xv = xin[(size_t)(bg0 + tid) * T_LEN + 0];
    } else {
        v = g_h[((size_t)(bg0 + eb) * T_LEN + 0) * NU + eu];
    }

    for (int t = 0; t < T_LEN; ++t) {
        // (1) stage input rows of A (duplicated (a,a) pairs)
        if (KX == 1) {
            if (tid < NB) *(float2*)&Ash[2 * tid] = make_float2(xv, xv);
        } else {
            *(float2*)&Ash[eu * APITCH + 2 * eb] = make_float2(v, v);
        }
        __syncthreads();   // B1: A complete (h rows from prev epilogue, x rows now)

        // (2) prefetch next step's input (hidden under matmul)
        const int tn = (t + 1 < T_LEN) ? t + 1 : T_LEN - 1;
        if (KX == 1) {
            if (tid < NB) xv = xin[(size_t)(bg0 + tid) * T_LEN + tn];
        } else {
            v = g_h[((size_t)(bg0 + eb) * T_LEN + tn) * NU + eu];
        }

        // (3) matmul: 2 rows x 2 cols per thread, K = KTOT
        ull a0 = bpair, a1 = bpair;
        const float* wp = Wsh + 2 * j2;
        const float* ap = Ash + 4 * rq;
        #pragma unroll 16
        for (int k = 0; k < KTOT; ++k) {
            ull w = *(const ull*)(wp + (size_t)k * 256);         // cols 2j2,2j2+1
            ulonglong2 A = *(const ulonglong2*)(ap + k * APITCH); // rows 2rq,2rq+1 dup
            a0 = ffma2(A.x, w, a0);
            a1 = ffma2(A.y, w, a1);
        }

        // (4) scatter z to shared
        {
            float* zb = Zsh + (2 * rq) * 256 + 2 * j2;
            *(ull*)(zb)       = a0;   // row 2rq
            *(ull*)(zb + 256) = a1;   // row 2rq+1
        }
        __syncthreads();   // B2: Z complete; all A reads done

        // (5) epilogue: 1 cell per thread
        {
            const float* zr = Zsh + eb * 256 + eu;
            float zi = zr[0], zf = zr[64], zg = zr[128], zo = zr[192];
            float c_new = fmaf(sigf(zf), cs, sigf(zi) * fmaxf(zg, 0.0f));
            cs = c_new;
            float h = sigf(zo) * fmaxf(c_new, 0.0f);
            *(float2*)&Ash[(KX + eu) * APITCH + 2 * eb] = make_float2(h, h);
            if (!LAST || t == T_LEN - 1)
                g_h[((size_t)(bg0 + eb) * T_LEN + t) * NU + eu] = h;
        }
        // next iter's B1 orders epilogue writes before matmul reads
    }
}

__global__ void __launch_bounds__(256)
head_kernel(const float* __restrict__ Wd, const float* __restrict__ bd,
            float* __restrict__ out)
{
    __shared__ float wd[NU];
    if (threadIdx.x < NU) wd[threadIdx.x] = Wd[threadIdx.x];
    __syncthreads();
    int b = blockIdx.x * blockDim.x + threadIdx.x;
    const float* hp = g_h + ((size_t)b * T_LEN + (T_LEN - 1)) * NU;
    float s = 0.0f;
    #pragma unroll
    for (int u = 0; u < NU; ++u) s += hp[u] * wd[u];
    out[b] = s + bd[0];
}

extern "C" void kernel_launch(void* const* d_in, const int* in_sizes, int n_in,
                              void* d_out, int out_size)
{
    const float* x   = (const float*)d_in[0];
    const float* Wx0 = (const float*)d_in[1];
    const float* U0  = (const float*)d_in[2];
    const float* b0  = (const float*)d_in[3];
    const float* Wx1 = (const float*)d_in[4];
    const float* U1  = (const float*)d_in[5];
    const float* b1  = (const float*)d_in[6];
    const float* Wx2 = (const float*)d_in[7];
    const float* U2  = (const float*)d_in[8];
    const float* b2  = (const float*)d_in[9];
    const float* Wx3 = (const float*)d_in[10];
    const float* U3  = (const float*)d_in[11];
    const float* b3  = (const float*)d_in[12];
    const float* Wd  = (const float*)d_in[13];
    const float* bd  = (const float*)d_in[14];
    float* out = (float*)d_out;

    const int KT0 = 1 + NU, KT1 = 64 + NU;
    const size_t smem0 = (size_t)(KT0 * 256 + KT0 * APITCH + 8 * 256) * 4;
    const size_t smem1 = (size_t)(KT1 * 256 + KT1 * APITCH + 8 * 256) * 4;

    cudaFuncSetAttribute((const void*)lstm_layer<1, false>,
                         cudaFuncAttributeMaxDynamicSharedMemorySize, (int)smem0);
    cudaFuncSetAttribute((const void*)lstm_layer<64, false>,
                         cudaFuncAttributeMaxDynamicSharedMemorySize, (int)smem1);
    cudaFuncSetAttribute((const void*)lstm_layer<64, true>,
                         cudaFuncAttributeMaxDynamicSharedMemorySize, (int)smem1);

    lstm_layer<1,  false><<<NCTA, THR, smem0>>>(x,       Wx0, U0, b0);
    lstm_layer<64, false><<<NCTA, THR, smem1>>>(nullptr, Wx1, U1, b1);
    lstm_layer<64, false><<<NCTA, THR, smem1>>>(nullptr, Wx2, U2, b2);
    lstm_layer<64, true ><<<NCTA, THR, smem1>>>(nullptr, Wx3, U3, b3);
    head_kernel<<<B_TOT / 256, 256>>>(Wd, bd, out);
}

// round 4
// speedup vs baseline: 1.7237x; 1.7237x over previous
#include <cuda_runtime.h>
#include <cstdint>

typedef unsigned long long ull;

#define B_TOT 1024
#define T_LEN 512
#define NU    64
#define NB    8
#define NCTA  128
#define THR   512

// Layer activation ping-pong buffer: h[b][t][u], 128 MiB.
__device__ float g_h[(size_t)B_TOT * T_LEN * NU];

__device__ __forceinline__ ull ffma2(ull a, ull b, ull c) {
    ull d;
    asm("fma.rn.f32x2 %0, %1, %2, %3;" : "=l"(d) : "l"(a), "l"(b), "l"(c));
    return d;
}
__device__ __forceinline__ ull packf2(float lo, float hi) {
    ull d;
    asm("mov.b64 %0, {%1, %2};" : "=l"(d) : "f"(lo), "f"(hi));
    return d;
}
__device__ __forceinline__ float2 unpackf2(ull v) {
    float2 r;
    asm("mov.b64 {%0, %1}, %2;" : "=f"(r.x), "=f"(r.y) : "l"(v));
    return r;
}
// sigmoid(x) = 0.5*tanh(0.5x) + 0.5 : one MUFU + FMA
__device__ __forceinline__ float sigf(float x) {
    float t;
    asm("tanh.approx.f32 %0, %1;" : "=f"(t) : "f"(0.5f * x));
    return fmaf(0.5f, t, 0.5f);
}

// KX = 64 for layers 1-3 (x-part = prev layer h); 0 for layer 0 (x is scalar,
// folded as a rank-1 update into the epilogue). Matmul K = KX + 64.
// Thread (c = tid&255, kh = tid>>8) owns column c, K-half kh; W slice lives in
// registers as (w_k, w_{k+1}) pairs; acc holds (even-k, odd-k) partial sums.
template <int KX, bool LAST>
__global__ void __launch_bounds__(THR, 1)
lstm_layer(const float* __restrict__ xin, const float* __restrict__ Wx,
           const float* __restrict__ U,   const float* __restrict__ bias)
{
    constexpr int KTOT = KX + NU;    // 128 or 64
    constexpr int KH   = KTOT / 2;   // 64 or 32 (k's per thread)
    constexpr int NP   = KH / 2;     // 32 or 16 ull weight pairs
    constexpr int AP   = KTOT + 4;   // A row pitch (16B aligned: 132/68 floats)

    __shared__ float Ash[NB][AP];        // A[row][k]; x-part k<KX, h-part k>=KX
    __shared__ float Zsh[2][NB][256];    // per-kh partial z
    __shared__ float Xsh[NB];            // layer0 scalar inputs

    const int tid = threadIdx.x;
    const int c   = tid & 255;           // owned column
    const int kh  = tid >> 8;            // K-half
    const int k0  = kh * KH;
    const int bg0 = blockIdx.x * NB;
    const int eb  = tid >> 6;            // epilogue cell batch row (0..7)
    const int eu  = tid & 63;            // epilogue cell unit

    // ---- stage W slice into registers (one-time) ----
    ull w[NP];
    #pragma unroll
    for (int kk = 0; kk < NP; ++kk) {
        const int k = k0 + 2 * kk;
        float f0 = (k     < KX) ? Wx[(size_t)k * 256 + c]
                                : U[(size_t)(k - KX) * 256 + c];
        float f1 = (k + 1 < KX) ? Wx[(size_t)(k + 1) * 256 + c]
                                : U[(size_t)(k + 1 - KX) * 256 + c];
        w[kk] = packf2(f0, f1);
    }

    // ---- per-cell constants: bias (+ layer0 Wx row) ----
    float bg[4], wxg[4];
    #pragma unroll
    for (int g = 0; g < 4; ++g) {
        bg[g] = bias[eu + 64 * g];
        wxg[g] = (KX == 0) ? Wx[eu + 64 * g] : 0.0f;
    }

    // zero A (h0 = 0)
    for (int i = tid; i < NB * AP; i += THR) (&Ash[0][0])[i] = 0.0f;

    // ---- initial prefetch (t = 0) ----
    float v = 0.0f, xv = 0.0f;
    if (KX == 0) {
        if (tid < NB) xv = xin[(size_t)(bg0 + tid) * T_LEN + 0];
    } else {
        v = g_h[((size_t)(bg0 + eb) * T_LEN + 0) * NU + eu];
    }
    float cs = 0.0f;

    for (int t = 0; t < T_LEN; ++t) {
        // (1) stage this step's input
        if (KX == 0) {
            if (tid < NB) Xsh[tid] = xv;
        } else {
            Ash[eb][eu] = v;
        }
        __syncthreads();   // B1: A complete (h rows from prev epilogue)

        // (2) prefetch next step's input (hidden under matmul)
        const int tn = (t + 1 < T_LEN) ? t + 1 : T_LEN - 1;
        if (KX == 0) {
            if (tid < NB) xv = xin[(size_t)(bg0 + tid) * T_LEN + tn];
        } else {
            v = g_h[((size_t)(bg0 + eb) * T_LEN + tn) * NU + eu];
        }

        // (3) matmul: 8 rows x 1 col x KH k's; W from registers,
        //     A via broadcast LDS.128 (4 k's per load, zero duplication)
        ull acc[NB] = {0, 0, 0, 0, 0, 0, 0, 0};
        #pragma unroll
        for (int kk = 0; kk < KH; kk += 4) {
            #pragma unroll
            for (int r = 0; r < NB; ++r) {
                ulonglong2 a = *(const ulonglong2*)&Ash[r][k0 + kk];
                acc[r] = ffma2(a.x, w[kk / 2],     acc[r]);
                acc[r] = ffma2(a.y, w[kk / 2 + 1], acc[r]);
            }
        }
        #pragma unroll
        for (int r = 0; r < NB; ++r) {
            float2 p = unpackf2(acc[r]);
            Zsh[kh][r][c] = p.x + p.y;
        }
        __syncthreads();   // B2: Z complete; all A reads done

        // (4) epilogue: one cell per thread
        {
            float zi = Zsh[0][eb][eu]       + Zsh[1][eb][eu]       + bg[0];
            float zf = Zsh[0][eb][eu + 64]  + Zsh[1][eb][eu + 64]  + bg[1];
            float zg = Zsh[0][eb][eu + 128] + Zsh[1][eb][eu + 128] + bg[2];
            float zo = Zsh[0][eb][eu + 192] + Zsh[1][eb][eu + 192] + bg[3];
            if (KX == 0) {   // rank-1 x contribution (F = 1)
                float xr = Xsh[eb];
                zi = fmaf(xr, wxg[0], zi);
                zf = fmaf(xr, wxg[1], zf);
                zg = fmaf(xr, wxg[2], zg);
                zo = fmaf(xr, wxg[3], zo);
            }
            float cn = fmaf(sigf(zf), cs, sigf(zi) * fmaxf(zg, 0.0f));
            cs = cn;
            float h = sigf(zo) * fmaxf(cn, 0.0f);
            Ash[eb][KX + eu] = h;   // h-part for next step
            if (!LAST || t == T_LEN - 1)
                g_h[((size_t)(bg0 + eb) * T_LEN + t) * NU + eu] = h;
        }
        // next iter's B1 orders epilogue writes before matmul reads
    }
}

__global__ void __launch_bounds__(256)
head_kernel(const float* __restrict__ Wd, const float* __restrict__ bd,
            float* __restrict__ out)
{
    __shared__ float wd[NU];
    if (threadIdx.x < NU) wd[threadIdx.x] = Wd[threadIdx.x];
    __syncthreads();
    int b = blockIdx.x * blockDim.x + threadIdx.x;
    const float* hp = g_h + ((size_t)b * T_LEN + (T_LEN - 1)) * NU;
    float s = 0.0f;
    #pragma unroll
    for (int u = 0; u < NU; ++u) s += hp[u] * wd[u];
    out[b] = s + bd[0];
}

extern "C" void kernel_launch(void* const* d_in, const int* in_sizes, int n_in,
                              void* d_out, int out_size)
{
    const float* x   = (const float*)d_in[0];
    const float* Wx0 = (const float*)d_in[1];
    const float* U0  = (const float*)d_in[2];
    const float* b0  = (const float*)d_in[3];
    const float* Wx1 = (const float*)d_in[4];
    const float* U1  = (const float*)d_in[5];
    const float* b1  = (const float*)d_in[6];
    const float* Wx2 = (const float*)d_in[7];
    const float* U2  = (const float*)d_in[8];
    const float* b2  = (const float*)d_in[9];
    const float* Wx3 = (const float*)d_in[10];
    const float* U3  = (const float*)d_in[11];
    const float* b3  = (const float*)d_in[12];
    const float* Wd  = (const float*)d_in[13];
    const float* bd  = (const float*)d_in[14];
    float* out = (float*)d_out;

    lstm_layer<0,  false><<<NCTA, THR>>>(x,       Wx0, U0, b0);
    lstm_layer<64, false><<<NCTA, THR>>>(nullptr, Wx1, U1, b1);
    lstm_layer<64, false><<<NCTA, THR>>>(nullptr, Wx2, U2, b2);
    lstm_layer<64, true ><<<NCTA, THR>>>(nullptr, Wx3, U3, b3);
    head_kernel<<<B_TOT / 256, 256>>>(Wd, bd, out);
}

// round 5
// speedup vs baseline: 2.1614x; 1.2540x over previous
#include <cuda_runtime.h>
#include <cstdint>

typedef unsigned long long ull;

#define B_TOT 1024
#define T_LEN 512
#define NU    64
#define NB    8
#define NCTA  128
#define THR   512

// Layer activation ping-pong buffer: h[b][t][u], 128 MiB.
__device__ float g_h[(size_t)B_TOT * T_LEN * NU];

__device__ __forceinline__ ull ffma2(ull a, ull b, ull c) {
    ull d;
    asm("fma.rn.f32x2 %0, %1, %2, %3;" : "=l"(d) : "l"(a), "l"(b), "l"(c));
    return d;
}
__device__ __forceinline__ ull packf2(float lo, float hi) {
    ull d;
    asm("mov.b64 %0, {%1, %2};" : "=l"(d) : "f"(lo), "f"(hi));
    return d;
}
__device__ __forceinline__ float2 unpackf2(ull v) {
    float2 r;
    asm("mov.b64 {%0, %1}, %2;" : "=f"(r.x), "=f"(r.y) : "l"(v));
    return r;
}
// sigmoid(x) = 0.5*tanh(0.5x) + 0.5 : one MUFU + FMA
__device__ __forceinline__ float sigf(float x) {
    float t;
    asm("tanh.approx.f32 %0, %1;" : "=f"(t) : "f"(0.5f * x));
    return fmaf(0.5f, t, 0.5f);
}

// KX = 64 for layers 1-3 (x-part = prev layer h); 0 for layer 0 (scalar x
// folded as rank-1 update into the epilogue). Matmul K = KX + 64.
// Lane owns 2 adjacent columns (2m, 2m+1) and a K-quarter; W in registers as
// (w_k, w_{k+1}) pairs; acc holds (even-k, odd-k) partial sums (no A dup).
template <int KX, bool LAST>
__global__ void __launch_bounds__(THR, 1)
lstm_layer(const float* __restrict__ xin, const float* __restrict__ Wx,
           const float* __restrict__ U,   const float* __restrict__ bias)
{
    constexpr int KTOT = KX + NU;    // 128 or 64
    constexpr int KH   = KTOT / 4;   // k's per lane: 32 or 16
    constexpr int NP   = KH / 2;     // ull weight pairs per column: 16 or 8
    constexpr int AP   = KTOT + 4;   // A row pitch, 16B-aligned

    __shared__ float Ash[NB][AP];        // A[row][k]; x-part k<KX, h-part k>=KX
    __shared__ float Zsh[4][NB][256];    // per-kq partial z
    __shared__ float Xsh[NB];            // layer0 scalar inputs

    const int tid = threadIdx.x;
    const int m   = tid & 127;           // column pair: cols 2m, 2m+1
    const int c0  = 2 * m;
    const int kq  = tid >> 7;            // K-quarter 0..3
    const int k0  = kq * KH;
    const int bg0 = blockIdx.x * NB;
    const int eb  = tid >> 6;            // epilogue cell batch row (0..7)
    const int eu  = tid & 63;            // epilogue cell unit

    // ---- stage W slices into registers (one-time) ----
    ull w0[NP], w1[NP];
    #pragma unroll
    for (int j = 0; j < NP; ++j) {
        const int k = k0 + 2 * j;
        const float* r0 = (k     < KX) ? Wx + (size_t)k * 256
                                       : U  + (size_t)(k - KX) * 256;
        const float* r1 = (k + 1 < KX) ? Wx + (size_t)(k + 1) * 256
                                       : U  + (size_t)(k + 1 - KX) * 256;
        w0[j] = packf2(r0[c0],     r1[c0]);
        w1[j] = packf2(r0[c0 + 1], r1[c0 + 1]);
    }

    // ---- per-cell constants: bias (+ layer0 Wx row, F = 1) ----
    float bg[4], wxg[4];
    #pragma unroll
    for (int g = 0; g < 4; ++g) {
        bg[g]  = bias[eu + 64 * g];
        wxg[g] = (KX == 0) ? Wx[eu + 64 * g] : 0.0f;
    }

    // zero A (h0 = 0)
    for (int i = tid; i < NB * AP; i += THR) (&Ash[0][0])[i] = 0.0f;

    // ---- initial prefetch (t = 0) ----
    float v = 0.0f, xv = 0.0f;
    if (KX == 0) {
        if (tid < NB) xv = xin[(size_t)(bg0 + tid) * T_LEN + 0];
    } else {
        v = g_h[((size_t)(bg0 + eb) * T_LEN + 0) * NU + eu];
    }
    float cs = 0.0f;

    for (int t = 0; t < T_LEN; ++t) {
        // (1) stage this step's input
        if (KX == 0) {
            if (tid < NB) Xsh[tid] = xv;
        } else {
            Ash[eb][eu] = v;
        }
        __syncthreads();   // B1: A complete (h rows from prev epilogue)

        // (2) prefetch next step's input (hidden under matmul)
        const int tn = (t + 1 < T_LEN) ? t + 1 : T_LEN - 1;
        if (KX == 0) {
            if (tid < NB) xv = xin[(size_t)(bg0 + tid) * T_LEN + tn];
        } else {
            v = g_h[((size_t)(bg0 + eb) * T_LEN + tn) * NU + eu];
        }

        // (3) matmul: 8 rows x 2 cols x KH k's; W in regs, A broadcast LDS.128
        ull a0[NB] = {0,0,0,0,0,0,0,0};   // col c0, (even,odd)-k partials
        ull a1[NB] = {0,0,0,0,0,0,0,0};   // col c0+1
        #pragma unroll
        for (int kk = 0; kk < KH; kk += 4) {
            #pragma unroll
            for (int r = 0; r < NB; ++r) {
                ulonglong2 a = *(const ulonglong2*)&Ash[r][k0 + kk];
                a0[r] = ffma2(a.x, w0[kk / 2],     a0[r]);
                a0[r] = ffma2(a.y, w0[kk / 2 + 1], a0[r]);
                a1[r] = ffma2(a.x, w1[kk / 2],     a1[r]);
                a1[r] = ffma2(a.y, w1[kk / 2 + 1], a1[r]);
            }
        }
        #pragma unroll
        for (int r = 0; r < NB; ++r) {
            float2 p0 = unpackf2(a0[r]);
            float2 p1 = unpackf2(a1[r]);
            *(float2*)&Zsh[kq][r][c0] = make_float2(p0.x + p0.y, p1.x + p1.y);
        }
        __syncthreads();   // B2: Z complete; all A reads done

        // (4) epilogue: one cell per thread, reduce 4 K-quarter partials
        {
            float zi = bg[0], zf = bg[1], zg = bg[2], zo = bg[3];
            #pragma unroll
            for (int q = 0; q < 4; ++q) {
                zi += Zsh[q][eb][eu];
                zf += Zsh[q][eb][eu + 64];
                zg += Zsh[q][eb][eu + 128];
                zo += Zsh[q][eb][eu + 192];
            }
            if (KX == 0) {   // rank-1 x contribution (F = 1)
                float xr = Xsh[eb];
                zi = fmaf(xr, wxg[0], zi);
                zf = fmaf(xr, wxg[1], zf);
                zg = fmaf(xr, wxg[2], zg);
                zo = fmaf(xr, wxg[3], zo);
            }
            float cn = fmaf(sigf(zf), cs, sigf(zi) * fmaxf(zg, 0.0f));
            cs = cn;
            float h = sigf(zo) * fmaxf(cn, 0.0f);
            Ash[eb][KX + eu] = h;   // h-part for next step
            if (!LAST || t == T_LEN - 1)
                g_h[((size_t)(bg0 + eb) * T_LEN + t) * NU + eu] = h;
        }
        // next iter's B1 orders epilogue writes before matmul reads
    }
}

__global__ void __launch_bounds__(256)
head_kernel(const float* __restrict__ Wd, const float* __restrict__ bd,
            float* __restrict__ out)
{
    __shared__ float wd[NU];
    if (threadIdx.x < NU) wd[threadIdx.x] = Wd[threadIdx.x];
    __syncthreads();
    int b = blockIdx.x * blockDim.x + threadIdx.x;
    const float* hp = g_h + ((size_t)b * T_LEN + (T_LEN - 1)) * NU;
    float s = 0.0f;
    #pragma unroll
    for (int u = 0; u < NU; ++u) s += hp[u] * wd[u];
    out[b] = s + bd[0];
}

extern "C" void kernel_launch(void* const* d_in, const int* in_sizes, int n_in,
                              void* d_out, int out_size)
{
    const float* x   = (const float*)d_in[0];
    const float* Wx0 = (const float*)d_in[1];
    const float* U0  = (const float*)d_in[2];
    const float* b0  = (const float*)d_in[3];
    const float* Wx1 = (const float*)d_in[4];
    const float* U1  = (const float*)d_in[5];
    const float* b1  = (const float*)d_in[6];
    const float* Wx2 = (const float*)d_in[7];
    const float* U2  = (const float*)d_in[8];
    const float* b2  = (const float*)d_in[9];
    const float* Wx3 = (const float*)d_in[10];
    const float* U3  = (const float*)d_in[11];
    const float* b3  = (const float*)d_in[12];
    const float* Wd  = (const float*)d_in[13];
    const float* bd  = (const float*)d_in[14];
    float* out = (float*)d_out;

    lstm_layer<0,  false><<<NCTA, THR>>>(x,       Wx0, U0, b0);
    lstm_layer<64, false><<<NCTA, THR>>>(nullptr, Wx1, U1, b1);
    lstm_layer<64, false><<<NCTA, THR>>>(nullptr, Wx2, U2, b2);
    lstm_layer<64, true ><<<NCTA, THR>>>(nullptr, Wx3, U3, b3);
    head_kernel<<<B_TOT / 256, 256>>>(Wd, bd, out);
}

// round 7
// speedup vs baseline: 4.2957x; 1.9875x over previous
#include <cuda_runtime.h>
#include <cuda_bf16.h>
#include <cstdint>

typedef unsigned long long ull;

#define B_TOT 1024
#define T_LEN 512
#define NU    64
#define NB    8
#define NCTA  128
#define THR   512

// Layer activation ping-pong buffer: h[b][t][u], 128 MiB.
__device__ float g_h[(size_t)B_TOT * T_LEN * NU];

__device__ __forceinline__ float sigf(float x) {
    float t; asm("tanh.approx.f32 %0, %1;" : "=f"(t) : "f"(0.5f * x));
    return fmaf(0.5f, t, 0.5f);
}
// pack two bf16 (k, k+1) into one frag register (low half = lower k)
__device__ __forceinline__ uint32_t pack_bf2(__nv_bfloat16 a, __nv_bfloat16 b) {
    __nv_bfloat162 p; p.x = a; p.y = b;
    return *(uint32_t*)&p;
}
__device__ __forceinline__ void hmma(float* c, const uint32_t* a, uint32_t b0, uint32_t b1) {
    asm volatile(
        "mma.sync.aligned.m16n8k16.row.col.f32.bf16.bf16.f32 "
        "{%0,%1,%2,%3}, {%4,%5,%6,%7}, {%8,%9}, {%0,%1,%2,%3};"
        : "+f"(c[0]), "+f"(c[1]), "+f"(c[2]), "+f"(c[3])
        : "r"(a[0]), "r"(a[1]), "r"(a[2]), "r"(a[3]), "r"(b0), "r"(b1));
}

// KX = 64 for layers 1-3 (x-part = prev-layer h), 0 for layer 0 (scalar x
// folded as rank-1 update in epilogue). Logical K = KX+64.
// act tile: [8 batch][P] bf16, k<KTOT = hi block, k>=KTOT = lo block.
// Warp w computes gates [16w,16w+16) x 8 batches via 24 (or 12) HMMAs with
// W fragments resident in registers; z = Whi*Ahi + Whi*Alo + Wlo*Ahi.
template <int KX, bool LAST>
__global__ void __launch_bounds__(THR, 1)
lstm_layer(const float* __restrict__ xin, const float* __restrict__ Wx,
           const float* __restrict__ U,   const float* __restrict__ bias)
{
    constexpr int KTOT   = KX + NU;       // 128 or 64
    constexpr int KSTEPS = KTOT / 16;     // 8 or 4
    constexpr int KEXT   = 2 * KTOT;
    constexpr int P      = KEXT + 8;      // bf16 pitch -> conflict-free B loads

    __shared__ __nv_bfloat16 act[NB * P];
    __shared__ float Zsh[256 * 9];        // [gate m][batch n], pitch 9
    __shared__ float Xsh[NB];

    const int tid  = threadIdx.x;
    const int wid  = tid >> 5;
    const int lane = tid & 31;
    const int lr   = lane >> 2;           // fragment row group 0..7
    const int qq   = lane & 3;            // fragment quad col 0..3
    const int bg0  = blockIdx.x * NB;
    const int eb   = tid >> 6;            // epilogue cell batch row 0..7
    const int eu   = tid & 63;            // epilogue cell unit

    // ---- stage W fragments into registers (one-time) ----
    // A-frag m16n8k16 lane map: a0:(m=lr,   k=kb+2qq,+1)  a1:(m=lr+8, same k)
    //                           a2:(m=lr,   k+8)          a3:(m=lr+8, k+8)
    uint32_t Whi[KSTEPS][4], Wlo[KSTEPS][4];
    {
        const int m0 = 16 * wid + lr, m1 = m0 + 8;
        #pragma unroll
        for (int s = 0; s < KSTEPS; ++s) {
            const int kb = 16 * s + 2 * qq;
            #pragma unroll
            for (int i = 0; i < 4; ++i) {
                const int k = kb + ((i >> 1) << 3);     // +8 for a2,a3
                const int m = (i & 1) ? m1 : m0;
                float f0 = (k     < KX) ? Wx[(size_t)k * 256 + m]
                                        : U[(size_t)(k - KX) * 256 + m];
                float f1 = (k + 1 < KX) ? Wx[(size_t)(k + 1) * 256 + m]
                                        : U[(size_t)(k + 1 - KX) * 256 + m];
                __nv_bfloat16 h0 = __float2bfloat16(f0), h1 = __float2bfloat16(f1);
                __nv_bfloat16 l0 = __float2bfloat16(f0 - __bfloat162float(h0));
                __nv_bfloat16 l1 = __float2bfloat16(f1 - __bfloat162float(h1));
                Whi[s][i] = pack_bf2(h0, h1);
                Wlo[s][i] = pack_bf2(l0, l1);
            }
        }
    }

    // per-cell constants
    float bg[4], wxg[4];
    #pragma unroll
    for (int g = 0; g < 4; ++g) {
        bg[g]  = bias[eu + 64 * g];
        wxg[g] = (KX == 0) ? Wx[eu + 64 * g] : 0.0f;
    }

    // zero act (h0 = 0, lo block too)
    for (int i = tid; i < NB * P; i += THR) act[i] = __float2bfloat16(0.0f);

    // ---- initial prefetch (t = 0): one cell per thread ----
    float v = 0.0f, xv = 0.0f, cs = 0.0f;
    if (KX == 0) {
        if (tid < NB) xv = xin[(size_t)(bg0 + tid) * T_LEN + 0];
    } else {
        v = g_h[((size_t)(bg0 + eb) * T_LEN + 0) * NU + eu];
    }

    // B-frag base: b0:(k=kb+2qq,+1, n=lane>>2) b1:(k+8)
    const int bn = lane >> 2;

    for (int t = 0; t < T_LEN; ++t) {
        // (1) stage x-part of act (layers>=1) / scalar x (layer0)
        if (KX == 0) {
            if (tid < NB) Xsh[tid] = xv;
        } else {
            __nv_bfloat16 h = __float2bfloat16(v);
            act[eb * P + eu]        = h;
            act[eb * P + KTOT + eu] = __float2bfloat16(v - __bfloat162float(h));
        }
        __syncthreads();   // B1: act tile complete

        // (2) prefetch next step's input
        const int tn = (t + 1 < T_LEN) ? t + 1 : T_LEN - 1;
        if (KX == 0) {
            if (tid < NB) xv = xin[(size_t)(bg0 + tid) * T_LEN + tn];
        } else {
            v = g_h[((size_t)(bg0 + eb) * T_LEN + tn) * NU + eu];
        }

        // (3) MMA: 3 hi/lo terms x KSTEPS, two accumulator chains
        float ce[4] = {0, 0, 0, 0}, co[4] = {0, 0, 0, 0};
        #pragma unroll
        for (int s = 0; s < KSTEPS; ++s) {
            const uint32_t* bp =
                (const uint32_t*)(act + bn * P + 16 * s + 2 * qq);
            uint32_t bh0 = bp[0], bh1 = bp[4];                 // hi block
            uint32_t bl0 = bp[KTOT / 2], bl1 = bp[KTOT / 2 + 4]; // lo block
            float* acc = (s & 1) ? co : ce;
            hmma(acc, Whi[s], bh0, bh1);
            hmma(acc, Whi[s], bl0, bl1);
            hmma(acc, Wlo[s], bh0, bh1);
        }
        // (4) scatter z to Zsh[m][n] (pitch 9)
        {
            const int m0 = 16 * wid + lr;
            const int n0 = 2 * qq;
            Zsh[m0 * 9 + n0]           = ce[0] + co[0];
            Zsh[m0 * 9 + n0 + 1]       = ce[1] + co[1];
            Zsh[(m0 + 8) * 9 + n0]     = ce[2] + co[2];
            Zsh[(m0 + 8) * 9 + n0 + 1] = ce[3] + co[3];
        }
        __syncthreads();   // B2: Zsh complete; all act reads done

        // (5) epilogue: one cell per thread
        {
            float zi = Zsh[eu * 9 + eb]         + bg[0];
            float zf = Zsh[(eu + 64) * 9 + eb]  + bg[1];
            float zg = Zsh[(eu + 128) * 9 + eb] + bg[2];
            float zo = Zsh[(eu + 192) * 9 + eb] + bg[3];
            if (KX == 0) {   // rank-1 x contribution (F = 1)
                float xr = Xsh[eb];
                zi = fmaf(xr, wxg[0], zi); zf = fmaf(xr, wxg[1], zf);
                zg = fmaf(xr, wxg[2], zg); zo = fmaf(xr, wxg[3], zo);
            }
            float cn = fmaf(sigf(zf), cs, sigf(zi) * fmaxf(zg, 0.0f));
            cs = cn;
            float h = sigf(zo) * fmaxf(cn, 0.0f);
            __nv_bfloat16 hh = __float2bfloat16(h);
            act[eb * P + KX + eu]        = hh;
            act[eb * P + KTOT + KX + eu] = __float2bfloat16(h - __bfloat162float(hh));
            if (!LAST || t == T_LEN - 1)
                g_h[((size_t)(bg0 + eb) * T_LEN + t) * NU + eu] = h;
        }
        // next iteration's B1 orders h stores before the MMA B-frag loads
    }
}

__global__ void __launch_bounds__(256)
head_kernel(const float* __restrict__ Wd, const float* __restrict__ bd,
            float* __restrict__ out)
{
    __shared__ float wd[NU];
    if (threadIdx.x < NU) wd[threadIdx.x] = Wd[threadIdx.x];
    __syncthreads();
    int b = blockIdx.x * blockDim.x + threadIdx.x;
    const float* hp = g_h + ((size_t)b * T_LEN + (T_LEN - 1)) * NU;
    float s = 0.0f;
    #pragma unroll
    for (int u = 0; u < NU; ++u) s += hp[u] * wd[u];
    out[b] = s + bd[0];
}

extern "C" void kernel_launch(void* const* d_in, const int* in_sizes, int n_in,
                              void* d_out, int out_size)
{
    const float* x   = (const float*)d_in[0];
    const float* Wx0 = (const float*)d_in[1];
    const float* U0  = (const float*)d_in[2];
    const float* b0  = (const float*)d_in[3];
    const float* Wx1 = (const float*)d_in[4];
    const float* U1  = (const float*)d_in[5];
    const float* b1  = (const float*)d_in[6];
    const float* Wx2 = (const float*)d_in[7];
    const float* U2  = (const float*)d_in[8];
    const float* b2  = (const float*)d_in[9];
    const float* Wx3 = (const float*)d_in[10];
    const float* U3  = (const float*)d_in[11];
    const float* b3  = (const float*)d_in[12];
    const float* Wd  = (const float*)d_in[13];
    const float* bd  = (const float*)d_in[14];
    float* out = (float*)d_out;

    lstm_layer<0,  false><<<NCTA, THR>>>(x,       Wx0, U0, b0);
    lstm_layer<64, false><<<NCTA, THR>>>(nullptr, Wx1, U1, b1);
    lstm_layer<64, false><<<NCTA, THR>>>(nullptr, Wx2, U2, b2);
    lstm_layer<64, true ><<<NCTA, THR>>>(nullptr, Wx3, U3, b3);
    head_kernel<<<B_TOT / 256, 256>>>(Wd, bd, out);
}

// round 8
// speedup vs baseline: 4.9846x; 1.1604x over previous
#include <cuda_runtime.h>
#include <cuda_bf16.h>
#include <cstdint>

typedef unsigned long long ull;

#define B_TOT 1024
#define T_LEN 512
#define NU    64
#define NB    8
#define NCTA  128
#define THR   512

// Layer activation ping-pong buffer: h[b][t][u], 128 MiB.
__device__ float g_h[(size_t)B_TOT * T_LEN * NU];

__device__ __forceinline__ float sigf(float x) {
    float t; asm("tanh.approx.f32 %0, %1;" : "=f"(t) : "f"(0.5f * x));
    return fmaf(0.5f, t, 0.5f);
}
__device__ __forceinline__ uint32_t pack_bf2(__nv_bfloat16 a, __nv_bfloat16 b) {
    __nv_bfloat162 p; p.x = a; p.y = b;
    return *(uint32_t*)&p;
}
__device__ __forceinline__ void hmma(float* c, const uint32_t* a, uint32_t b0, uint32_t b1) {
    asm volatile(
        "mma.sync.aligned.m16n8k16.row.col.f32.bf16.bf16.f32 "
        "{%0,%1,%2,%3}, {%4,%5,%6,%7}, {%8,%9}, {%0,%1,%2,%3};"
        : "+f"(c[0]), "+f"(c[1]), "+f"(c[2]), "+f"(c[3])
        : "r"(a[0]), "r"(a[1]), "r"(a[2]), "r"(a[3]), "r"(b0), "r"(b1));
}

// Gate-interleaved column space: column m <-> original column (m>>2) + 64*(m&3).
// Warp w owns gate-columns [16w, 16w+16) = units [4w, 4w+4) x all 4 gates.
// After the MMA, a 4x4 lane transpose (over lane bits 2-3) hands each lane the
// 4 gates of exactly one (batch, unit) cell; the LSTM pointwise step runs
// entirely in registers. One __syncthreads per step; act tile double-buffered.
// z = Whi*Ahi + Whi*Alo + Wlo*Ahi (bf16 hi/lo compensation, err ~2^-18).
template <int KX, bool LAST>
__global__ void __launch_bounds__(THR, 1)
lstm_layer(const float* __restrict__ xin, const float* __restrict__ Wx,
           const float* __restrict__ U,   const float* __restrict__ bias)
{
    constexpr int KTOT   = KX + NU;       // 128 or 64
    constexpr int KSTEPS = KTOT / 16;     // 8 or 4
    constexpr int P      = 2 * KTOT + 8;  // bf16 pitch -> conflict-free B loads

    __shared__ __nv_bfloat16 act[2][NB * P];  // [buf][batch][k]: hi block | lo block
    __shared__ float Xsh[2][NB];              // layer0 scalar inputs

    const int tid  = threadIdx.x;
    const int wid  = tid >> 5;
    const int lane = tid & 31;
    const int lr   = lane >> 2;           // fragment row group 0..7
    const int qq   = lane & 3;            // fragment quad col 0..3
    const int aa   = lr >> 2;             // lane bit4
    const int gg   = lr & 3;              // lane bits 2-3 (gate index pre-transpose)
    const int bg0  = blockIdx.x * NB;

    // cell owned by this lane after the transpose
    const int ul = aa + 2 * (gg >> 1);    // unit-local 0..3
    const int u  = 4 * wid + ul;          // unit 0..63
    const int b  = 2 * qq + (gg & 1);     // batch row 0..7

    // ---- stage W fragments (interleaved columns) into registers ----
    uint32_t Whi[KSTEPS][4], Wlo[KSTEPS][4];
    {
        const int m0 = 16 * wid + lr, m1 = m0 + 8;
        #pragma unroll
        for (int s = 0; s < KSTEPS; ++s) {
            const int kb = 16 * s + 2 * qq;
            #pragma unroll
            for (int i = 0; i < 4; ++i) {
                const int k = kb + ((i >> 1) << 3);
                const int m = (i & 1) ? m1 : m0;
                const int oc = (m >> 2) + 64 * (m & 3);   // original column
                float f0 = (k     < KX) ? Wx[(size_t)k * 256 + oc]
                                        : U[(size_t)(k - KX) * 256 + oc];
                float f1 = (k + 1 < KX) ? Wx[(size_t)(k + 1) * 256 + oc]
                                        : U[(size_t)(k + 1 - KX) * 256 + oc];
                __nv_bfloat16 h0 = __float2bfloat16(f0), h1 = __float2bfloat16(f1);
                Whi[s][i] = pack_bf2(h0, h1);
                Wlo[s][i] = pack_bf2(__float2bfloat16(f0 - __bfloat162float(h0)),
                                     __float2bfloat16(f1 - __bfloat162float(h1)));
            }
        }
    }

    // per-cell constants
    float bg[4], wxg[4];
    #pragma unroll
    for (int g = 0; g < 4; ++g) {
        bg[g]  = bias[u + 64 * g];
        wxg[g] = (KX == 0) ? Wx[u + 64 * g] : 0.0f;
    }

    // zero both act buffers (h0 = 0)
    for (int i = tid; i < 2 * NB * P; i += THR) act[0][i] = __float2bfloat16(0.0f);

    // ---- stage step-0 input into buf 0 ----
    float cs = 0.0f;
    if (KX == 0) {
        if (tid < NB) Xsh[0][tid] = xin[(size_t)(bg0 + tid) * T_LEN + 0];
    } else {
        float v0 = g_h[((size_t)(bg0 + b) * T_LEN + 0) * NU + u];
        __nv_bfloat16 xh = __float2bfloat16(v0);
        act[0][b * P + u]        = xh;
        act[0][b * P + KTOT + u] = __float2bfloat16(v0 - __bfloat162float(xh));
    }

    for (int t = 0; t < T_LEN; ++t) {
        const int p = t & 1;
        __syncthreads();   // buf[p] (act + Xsh) complete

        // prefetch step t+1 input (hidden under MMA)
        const int tn = (t + 1 < T_LEN) ? t + 1 : T_LEN - 1;
        float vn = 0.0f, xvn = 0.0f;
        if (KX == 0) {
            if (tid < NB) xvn = xin[(size_t)(bg0 + tid) * T_LEN + tn];
        } else {
            vn = g_h[((size_t)(bg0 + b) * T_LEN + tn) * NU + u];
        }

        // ---- MMA: 3 hi/lo terms x KSTEPS, 4 accumulator chains ----
        float a4[16] = {0,0,0,0, 0,0,0,0, 0,0,0,0, 0,0,0,0};
        const __nv_bfloat16* actp = act[p];
        #pragma unroll
        for (int s = 0; s < KSTEPS; ++s) {
            const uint32_t* bp = (const uint32_t*)(actp + lr * P + 16 * s + 2 * qq);
            uint32_t bh0 = bp[0], bh1 = bp[4];
            uint32_t bl0 = bp[KTOT / 2], bl1 = bp[KTOT / 2 + 4];
            float* acc = a4 + 4 * (s & 3);
            hmma(acc, Whi[s], bh0, bh1);
            hmma(acc, Whi[s], bl0, bl1);
            hmma(acc, Wlo[s], bh0, bh1);
        }
        float z0 = (a4[0] + a4[4])  + (a4[8]  + a4[12]);
        float z1 = (a4[1] + a4[5])  + (a4[9]  + a4[13]);
        float z2 = (a4[2] + a4[6])  + (a4[10] + a4[14]);
        float z3 = (a4[3] + a4[7])  + (a4[11] + a4[15]);

        // ---- 4x4 lane transpose over lane bits 2-3 (mirrored bfly) ----
        {
            const bool gb0 = (lane & 4) != 0;
            const bool gb1 = (lane & 8) != 0;
            float sA = gb0 ? z0 : z1, sB = gb0 ? z2 : z3;
            float tA = __shfl_xor_sync(0xffffffffu, sA, 4);
            float tB = __shfl_xor_sync(0xffffffffu, sB, 4);
            if (!gb0) { z1 = tA; z3 = tB; } else { z0 = tA; z2 = tB; }
            float sC = gb1 ? z0 : z2, sD = gb1 ? z1 : z3;
            float tC = __shfl_xor_sync(0xffffffffu, sC, 8);
            float tD = __shfl_xor_sync(0xffffffffu, sD, 8);
            if (!gb1) { z2 = tC; z3 = tD; } else { z0 = tC; z1 = tD; }
        }
        // lane now holds gates (i,f,g,o) = (z0,z1,z2,z3) of cell (b, u)

        // ---- epilogue (in registers) ----
        float zi = z0 + bg[0], zf = z1 + bg[1], zg = z2 + bg[2], zo = z3 + bg[3];
        if (KX == 0) {   // rank-1 x contribution (F = 1)
            float xr = Xsh[p][b];
            zi = fmaf(xr, wxg[0], zi); zf = fmaf(xr, wxg[1], zf);
            zg = fmaf(xr, wxg[2], zg); zo = fmaf(xr, wxg[3], zo);
        }
        float cn = fmaf(sigf(zf), cs, sigf(zi) * fmaxf(zg, 0.0f));
        cs = cn;
        float h = sigf(zo) * fmaxf(cn, 0.0f);

        // ---- write step t+1 operand tile (buf p^1) ----
        __nv_bfloat16* an = act[p ^ 1];
        __nv_bfloat16 hh = __float2bfloat16(h);
        an[b * P + KX + u]        = hh;
        an[b * P + KTOT + KX + u] = __float2bfloat16(h - __bfloat162float(hh));
        if (KX == 0) {
            if (tid < NB) Xsh[p ^ 1][tid] = xvn;
        } else {
            __nv_bfloat16 xh = __float2bfloat16(vn);
            an[b * P + u]        = xh;
            an[b * P + KTOT + u] = __float2bfloat16(vn - __bfloat162float(xh));
        }
        if (!LAST || t == T_LEN - 1)
            g_h[((size_t)(bg0 + b) * T_LEN + t) * NU + u] = h;
    }
}

__global__ void __launch_bounds__(256)
head_kernel(const float* __restrict__ Wd, const float* __restrict__ bd,
            float* __restrict__ out)
{
    __shared__ float wd[NU];
    if (threadIdx.x < NU) wd[threadIdx.x] = Wd[threadIdx.x];
    __syncthreads();
    int b = blockIdx.x * blockDim.x + threadIdx.x;
    const float* hp = g_h + ((size_t)b * T_LEN + (T_LEN - 1)) * NU;
    float s = 0.0f;
    #pragma unroll
    for (int u = 0; u < NU; ++u) s += hp[u] * wd[u];
    out[b] = s + bd[0];
}

extern "C" void kernel_launch(void* const* d_in, const int* in_sizes, int n_in,
                              void* d_out, int out_size)
{
    const float* x   = (const float*)d_in[0];
    const float* Wx0 = (const float*)d_in[1];
    const float* U0  = (const float*)d_in[2];
    const float* b0  = (const float*)d_in[3];
    const float* Wx1 = (const float*)d_in[4];
    const float* U1  = (const float*)d_in[5];
    const float* b1  = (const float*)d_in[6];
    const float* Wx2 = (const float*)d_in[7];
    const float* U2  = (const float*)d_in[8];
    const float* b2  = (const float*)d_in[9];
    const float* Wx3 = (const float*)d_in[10];
    const float* U3  = (const float*)d_in[11];
    const float* b3  = (const float*)d_in[12];
    const float* Wd  = (const float*)d_in[13];
    const float* bd  = (const float*)d_in[14];
    float* out = (float*)d_out;

    lstm_layer<0,  false><<<NCTA, THR>>>(x,       Wx0, U0, b0);
    lstm_layer<64, false><<<NCTA, THR>>>(nullptr, Wx1, U1, b1);
    lstm_layer<64, false><<<NCTA, THR>>>(nullptr, Wx2, U2, b2);
    lstm_layer<64, true ><<<NCTA, THR>>>(nullptr, Wx3, U3, b3);
    head_kernel<<<B_TOT / 256, 256>>>(Wd, bd, out);
}

// round 9
// speedup vs baseline: 4.9903x; 1.0011x over previous
#include <cuda_runtime.h>
#include <cuda_bf16.h>
#include <cstdint>

typedef unsigned long long ull;

#define B_TOT 1024
#define T_LEN 512
#define NU    64
#define NB    8
#define NCTA  128
#define THR   512

// Layer activation ping-pong buffer: h[b][t][u], 128 MiB.
__device__ float g_h[(size_t)B_TOT * T_LEN * NU];

__device__ __forceinline__ float sigf(float x) {
    float t; asm("tanh.approx.f32 %0, %1;" : "=f"(t) : "f"(0.5f * x));
    return fmaf(0.5f, t, 0.5f);
}
__device__ __forceinline__ uint32_t pack_bf2(__nv_bfloat16 a, __nv_bfloat16 b) {
    __nv_bfloat162 p; p.x = a; p.y = b;
    return *(uint32_t*)&p;
}
__device__ __forceinline__ void hmma(float* c, const uint32_t* a, uint32_t b0, uint32_t b1) {
    asm volatile(
        "mma.sync.aligned.m16n8k16.row.col.f32.bf16.bf16.f32 "
        "{%0,%1,%2,%3}, {%4,%5,%6,%7}, {%8,%9}, {%0,%1,%2,%3};"
        : "+f"(c[0]), "+f"(c[1]), "+f"(c[2]), "+f"(c[3])
        : "r"(a[0]), "r"(a[1]), "r"(a[2]), "r"(a[3]), "r"(b0), "r"(b1));
}

// Gate-interleaved column space: column m <-> original column (m>>2) + 64*(m&3).
// Warp w owns gate-columns [16w, 16w+16) = units [4w, 4w+4) x all 4 gates.
// After the MMA, a 4x4 lane transpose (over lane bits 2-3) hands each lane the
// 4 gates of exactly one (batch, unit) cell; the LSTM pointwise step runs
// entirely in registers. One __syncthreads per step; act tile double-buffered.
// z = Whi*Ahi + Whi*Alo + Wlo*Ahi (bf16 hi/lo compensation, err ~2^-18).
template <int KX, bool LAST>
__global__ void __launch_bounds__(THR, 1)
lstm_layer(const float* __restrict__ xin, const float* __restrict__ Wx,
           const float* __restrict__ U,   const float* __restrict__ bias)
{
    constexpr int KTOT   = KX + NU;       // 128 or 64
    constexpr int KSTEPS = KTOT / 16;     // 8 or 4
    constexpr int P      = 2 * KTOT + 8;  // bf16 pitch -> conflict-free B loads

    __shared__ __nv_bfloat16 act[2][NB * P];  // [buf][batch][k]: hi block | lo block
    __shared__ float Xsh[2][NB];              // layer0 scalar inputs

    const int tid  = threadIdx.x;
    const int wid  = tid >> 5;
    const int lane = tid & 31;
    const int lr   = lane >> 2;           // fragment row group 0..7
    const int qq   = lane & 3;            // fragment quad col 0..3
    const int aa   = lr >> 2;             // lane bit4
    const int gg   = lr & 3;              // lane bits 2-3 (gate index pre-transpose)
    const int bg0  = blockIdx.x * NB;

    // cell owned by this lane after the transpose
    const int ul = aa + 2 * (gg >> 1);    // unit-local 0..3
    const int u  = 4 * wid + ul;          // unit 0..63
    const int b  = 2 * qq + (gg & 1);     // batch row 0..7

    // ---- stage W fragments (interleaved columns) into registers ----
    uint32_t Whi[KSTEPS][4], Wlo[KSTEPS][4];
    {
        const int m0 = 16 * wid + lr, m1 = m0 + 8;
        #pragma unroll
        for (int s = 0; s < KSTEPS; ++s) {
            const int kb = 16 * s + 2 * qq;
            #pragma unroll
            for (int i = 0; i < 4; ++i) {
                const int k = kb + ((i >> 1) << 3);
                const int m = (i & 1) ? m1 : m0;
                const int oc = (m >> 2) + 64 * (m & 3);   // original column
                float f0 = (k     < KX) ? Wx[(size_t)k * 256 + oc]
                                        : U[(size_t)(k - KX) * 256 + oc];
                float f1 = (k + 1 < KX) ? Wx[(size_t)(k + 1) * 256 + oc]
                                        : U[(size_t)(k + 1 - KX) * 256 + oc];
                __nv_bfloat16 h0 = __float2bfloat16(f0), h1 = __float2bfloat16(f1);
                Whi[s][i] = pack_bf2(h0, h1);
                Wlo[s][i] = pack_bf2(__float2bfloat16(f0 - __bfloat162float(h0)),
                                     __float2bfloat16(f1 - __bfloat162float(h1)));
            }
        }
    }

    // per-cell constants
    float bg[4], wxg[4];
    #pragma unroll
    for (int g = 0; g < 4; ++g) {
        bg[g]  = bias[u + 64 * g];
        wxg[g] = (KX == 0) ? Wx[u + 64 * g] : 0.0f;
    }

    // zero both act buffers (h0 = 0)
    for (int i = tid; i < 2 * NB * P; i += THR) act[0][i] = __float2bfloat16(0.0f);

    // ---- stage step-0 input into buf 0 ----
    float cs = 0.0f;
    if (KX == 0) {
        if (tid < NB) Xsh[0][tid] = xin[(size_t)(bg0 + tid) * T_LEN + 0];
    } else {
        float v0 = g_h[((size_t)(bg0 + b) * T_LEN + 0) * NU + u];
        __nv_bfloat16 xh = __float2bfloat16(v0);
        act[0][b * P + u]        = xh;
        act[0][b * P + KTOT + u] = __float2bfloat16(v0 - __bfloat162float(xh));
    }

    for (int t = 0; t < T_LEN; ++t) {
        const int p = t & 1;
        __syncthreads();   // buf[p] (act + Xsh) complete

        // prefetch step t+1 input (hidden under MMA)
        const int tn = (t + 1 < T_LEN) ? t + 1 : T_LEN - 1;
        float vn = 0.0f, xvn = 0.0f;
        if (KX == 0) {
            if (tid < NB) xvn = xin[(size_t)(bg0 + tid) * T_LEN + tn];
        } else {
            vn = g_h[((size_t)(bg0 + b) * T_LEN + tn) * NU + u];
        }

        // ---- MMA: 3 hi/lo terms x KSTEPS, 4 accumulator chains ----
        float a4[16] = {0,0,0,0, 0,0,0,0, 0,0,0,0, 0,0,0,0};
        const __nv_bfloat16* actp = act[p];
        #pragma unroll
        for (int s = 0; s < KSTEPS; ++s) {
            const uint32_t* bp = (const uint32_t*)(actp + lr * P + 16 * s + 2 * qq);
            uint32_t bh0 = bp[0], bh1 = bp[4];
            uint32_t bl0 = bp[KTOT / 2], bl1 = bp[KTOT / 2 + 4];
            float* acc = a4 + 4 * (s & 3);
            hmma(acc, Whi[s], bh0, bh1);
            hmma(acc, Whi[s], bl0, bl1);
            hmma(acc, Wlo[s], bh0, bh1);
        }
        float z0 = (a4[0] + a4[4])  + (a4[8]  + a4[12]);
        float z1 = (a4[1] + a4[5])  + (a4[9]  + a4[13]);
        float z2 = (a4[2] + a4[6])  + (a4[10] + a4[14]);
        float z3 = (a4[3] + a4[7])  + (a4[11] + a4[15]);

        // ---- 4x4 lane transpose over lane bits 2-3 (mirrored bfly) ----
        {
            const bool gb0 = (lane & 4) != 0;
            const bool gb1 = (lane & 8) != 0;
            float sA = gb0 ? z0 : z1, sB = gb0 ? z2 : z3;
            float tA = __shfl_xor_sync(0xffffffffu, sA, 4);
            float tB = __shfl_xor_sync(0xffffffffu, sB, 4);
            if (!gb0) { z1 = tA; z3 = tB; } else { z0 = tA; z2 = tB; }
            float sC = gb1 ? z0 : z2, sD = gb1 ? z1 : z3;
            float tC = __shfl_xor_sync(0xffffffffu, sC, 8);
            float tD = __shfl_xor_sync(0xffffffffu, sD, 8);
            if (!gb1) { z2 = tC; z3 = tD; } else { z0 = tC; z1 = tD; }
        }
        // lane now holds gates (i,f,g,o) = (z0,z1,z2,z3) of cell (b, u)

        // ---- epilogue (in registers) ----
        float zi = z0 + bg[0], zf = z1 + bg[1], zg = z2 + bg[2], zo = z3 + bg[3];
        if (KX == 0) {   // rank-1 x contribution (F = 1)
            float xr = Xsh[p][b];
            zi = fmaf(xr, wxg[0], zi); zf = fmaf(xr, wxg[1], zf);
            zg = fmaf(xr, wxg[2], zg); zo = fmaf(xr, wxg[3], zo);
        }
        float cn = fmaf(sigf(zf), cs, sigf(zi) * fmaxf(zg, 0.0f));
        cs = cn;
        float h = sigf(zo) * fmaxf(cn, 0.0f);

        // ---- write step t+1 operand tile (buf p^1) ----
        __nv_bfloat16* an = act[p ^ 1];
        __nv_bfloat16 hh = __float2bfloat16(h);
        an[b * P + KX + u]        = hh;
        an[b * P + KTOT + KX + u] = __float2bfloat16(h - __bfloat162float(hh));
        if (KX == 0) {
            if (tid < NB) Xsh[p ^ 1][tid] = xvn;
        } else {
            __nv_bfloat16 xh = __float2bfloat16(vn);
            an[b * P + u]        = xh;
            an[b * P + KTOT + u] = __float2bfloat16(vn - __bfloat162float(xh));
        }
        if (!LAST || t == T_LEN - 1)
            g_h[((size_t)(bg0 + b) * T_LEN + t) * NU + u] = h;
    }
}

__global__ void __launch_bounds__(256)
head_kernel(const float* __restrict__ Wd, const float* __restrict__ bd,
            float* __restrict__ out)
{
    __shared__ float wd[NU];
    if (threadIdx.x < NU) wd[threadIdx.x] = Wd[threadIdx.x];
    __syncthreads();
    int b = blockIdx.x * blockDim.x + threadIdx.x;
    const float* hp = g_h + ((size_t)b * T_LEN + (T_LEN - 1)) * NU;
    float s = 0.0f;
    #pragma unroll
    for (int u = 0; u < NU; ++u) s += hp[u] * wd[u];
    out[b] = s + bd[0];
}

extern "C" void kernel_launch(void* const* d_in, const int* in_sizes, int n_in,
                              void* d_out, int out_size)
{
    const float* x   = (const float*)d_in[0];
    const float* Wx0 = (const float*)d_in[1];
    const float* U0  = (const float*)d_in[2];
    const float* b0  = (const float*)d_in[3];
    const float* Wx1 = (const float*)d_in[4];
    const float* U1  = (const float*)d_in[5];
    const float* b1  = (const float*)d_in[6];
    const float* Wx2 = (const float*)d_in[7];
    const float* U2  = (const float*)d_in[8];
    const float* b2  = (const float*)d_in[9];
    const float* Wx3 = (const float*)d_in[10];
    const float* U3  = (const float*)d_in[11];
    const float* b3  = (const float*)d_in[12];
    const float* Wd  = (const float*)d_in[13];
    const float* bd  = (const float*)d_in[14];
    float* out = (float*)d_out;

    lstm_layer<0,  false><<<NCTA, THR>>>(x,       Wx0, U0, b0);
    lstm_layer<64, false><<<NCTA, THR>>>(nullptr, Wx1, U1, b1);
    lstm_layer<64, false><<<NCTA, THR>>>(nullptr, Wx2, U2, b2);
    lstm_layer<64, true ><<<NCTA, THR>>>(nullptr, Wx3, U3, b3);
    head_kernel<<<B_TOT / 256, 256>>>(Wd, bd, out);
}